// round 17
// baseline (speedup 1.0000x reference)
#include <cuda_runtime.h>
#include <cstdint>

// ---------------- scratch (device globals; no allocation allowed) -------------
#define MAXN 50000
#define MAXE 500000

__device__ float g_xlr[(size_t)MAXN * 1024];  // [N][8*128]: (Wl|Wr) x 4 convs
__device__ float g_wcat[128 * 1024];          // packed weights [k][1024]
__device__ float g_bcat[512];                 // packed conv biases
__device__ float g_xcat[MAXN * 512];
__device__ float g_nsum[4 * MAXN * 16];       // per-conv segment sums

// ---------------- helpers -----------------------------------------------------

__device__ __forceinline__ uint32_t tf32u(float x) {
    uint32_t u; asm("cvt.rna.tf32.f32 %0, %1;" : "=r"(u) : "f"(x)); return u;
}
__device__ __forceinline__ float4 tf32cvt4(float4 v) {
    float4 r;
    r.x = __uint_as_float(tf32u(v.x));
    r.y = __uint_as_float(tf32u(v.y));
    r.z = __uint_as_float(tf32u(v.z));
    r.w = __uint_as_float(tf32u(v.w));
    return r;
}
__device__ __forceinline__ void mma_tf32(float* c, const uint32_t* a, const uint32_t* b) {
    asm volatile(
        "mma.sync.aligned.m16n8k8.row.col.f32.tf32.tf32.f32 "
        "{%0,%1,%2,%3}, {%4,%5,%6,%7}, {%8,%9}, {%0,%1,%2,%3};\n"
        : "+f"(c[0]), "+f"(c[1]), "+f"(c[2]), "+f"(c[3])
        : "r"(a[0]), "r"(a[1]), "r"(a[2]), "r"(a[3]), "r"(b[0]), "r"(b[1]));
}

// pack 8 [128,128] weight mats into wcat[k][w*128+j]; biases into bcat
__global__ void pack_w(const float* __restrict__ w0, const float* __restrict__ w1,
                       const float* __restrict__ w2, const float* __restrict__ w3,
                       const float* __restrict__ w4, const float* __restrict__ w5,
                       const float* __restrict__ w6, const float* __restrict__ w7,
                       float* __restrict__ wcat,
                       const float* __restrict__ b0, const float* __restrict__ b1,
                       const float* __restrict__ b2, const float* __restrict__ b3,
                       float* __restrict__ bcat) {
    int idx = blockIdx.x * blockDim.x + threadIdx.x;
    if (idx < 512) {
        const float* bs[4] = {b0, b1, b2, b3};
        bcat[idx] = bs[idx >> 7][idx & 127];
    }
    if (idx >= 128 * 1024) return;
    int w = (idx >> 14), rem = idx & 16383;
    int k = rem >> 7, j = rem & 127;
    const float* ws[8] = {w0, w1, w2, w3, w4, w5, w6, w7};
    wcat[k * 1024 + w * 128 + j] = ws[w][k * 128 + j];
}

// ---------------- tf32 tensor-core GEMM: out[M,NW] = A[M,K] @ W[K,NW] (+bias)
template <int K, int NW, int OSTRIDE>
__global__ __launch_bounds__(256)
void gemm_mma(const float* __restrict__ A, const float* __restrict__ W,
              const float* __restrict__ bias, float* __restrict__ out, int M) {
    __shared__ float As[128][36];   // [m][k]
    __shared__ float Ws[32][136];   // [k][n]

    const int tid = threadIdx.x;
    const int l = tid & 31, w = tid >> 5;
    const int g = l >> 2, tg = l & 3;
    const int wm = (w & 3) * 32;
    const int wn = (w >> 2) * 64;
    const int r0 = blockIdx.x * 128;
    const int c0 = blockIdx.y * 128;

    float c[2][8][4];
#pragma unroll
    for (int mt = 0; mt < 2; mt++)
#pragma unroll
        for (int nt = 0; nt < 8; nt++)
#pragma unroll
            for (int i = 0; i < 4; i++) c[mt][nt][i] = 0.f;

    for (int kt = 0; kt < K; kt += 32) {
#pragma unroll
        for (int i = 0; i < 4; i++) {
            int flat = tid + i * 256;
            int r = flat >> 3, kq = flat & 7;
            float4 v = (r0 + r < M)
                ? *(const float4*)&A[(size_t)(r0 + r) * K + kt + kq * 4]
                : make_float4(0.f, 0.f, 0.f, 0.f);
            *(float4*)&As[r][kq * 4] = tf32cvt4(v);
        }
#pragma unroll
        for (int i = 0; i < 4; i++) {
            int flat = tid + i * 256;
            int k = flat >> 5, n4 = flat & 31;
            float4 v = *(const float4*)&W[(size_t)(kt + k) * NW + c0 + n4 * 4];
            *(float4*)&Ws[k][n4 * 4] = tf32cvt4(v);
        }
        __syncthreads();

#pragma unroll
        for (int k8 = 0; k8 < 4; k8++) {
            const int kb = k8 * 8;
            uint32_t a[2][4], b[8][2];
#pragma unroll
            for (int mt = 0; mt < 2; mt++) {
                int m = wm + mt * 16;
                a[mt][0] = __float_as_uint(As[m + g][kb + tg]);
                a[mt][1] = __float_as_uint(As[m + 8 + g][kb + tg]);
                a[mt][2] = __float_as_uint(As[m + g][kb + tg + 4]);
                a[mt][3] = __float_as_uint(As[m + 8 + g][kb + tg + 4]);
            }
#pragma unroll
            for (int nt = 0; nt < 8; nt++) {
                int n = wn + nt * 8;
                b[nt][0] = __float_as_uint(Ws[kb + tg][n + g]);
                b[nt][1] = __float_as_uint(Ws[kb + tg + 4][n + g]);
            }
#pragma unroll
            for (int mt = 0; mt < 2; mt++)
#pragma unroll
                for (int nt = 0; nt < 8; nt++)
                    mma_tf32(c[mt][nt], a[mt], b[nt]);
        }
        __syncthreads();
    }

#pragma unroll
    for (int mt = 0; mt < 2; mt++) {
#pragma unroll
        for (int nt = 0; nt < 8; nt++) {
            int row = r0 + wm + mt * 16 + g;
            int col = c0 + wn + nt * 8 + tg * 2;
            float2 bv = bias ? *(const float2*)&bias[col] : make_float2(0.f, 0.f);
            if (row < M) {
                float2 o = make_float2(c[mt][nt][0] + bv.x, c[mt][nt][1] + bv.y);
                *(float2*)&out[(size_t)row * OSTRIDE + col] = o;
            }
            if (row + 8 < M) {
                float2 o = make_float2(c[mt][nt][2] + bv.x, c[mt][nt][3] + bv.y);
                *(float2*)&out[(size_t)(row + 8) * OSTRIDE + col] = o;
            }
        }
    }
}

// ---------------- fuse GEMM with inline xcat normalization ---------------------
__global__ __launch_bounds__(256)
void gemm_fuse(const float* __restrict__ A, const float* __restrict__ nsum,
               const float* __restrict__ bcat,
               const float* __restrict__ W, const float* __restrict__ bias,
               float* __restrict__ out, int M) {
    __shared__ float As[128][36];
    __shared__ float Ws[32][136];

    const int tid = threadIdx.x;
    const int l = tid & 31, w = tid >> 5;
    const int g = l >> 2, tg = l & 3;
    const int wm = (w & 3) * 32;
    const int wn = (w >> 2) * 64;
    const int r0 = blockIdx.x * 128;

    float c[2][8][4];
#pragma unroll
    for (int mt = 0; mt < 2; mt++)
#pragma unroll
        for (int nt = 0; nt < 8; nt++)
#pragma unroll
            for (int i = 0; i < 4; i++) c[mt][nt][i] = 0.f;

    for (int kt = 0; kt < 512; kt += 32) {
#pragma unroll
        for (int i = 0; i < 4; i++) {
            int flat = tid + i * 256;
            int r = flat >> 3, kq = flat & 7;
            int row = r0 + r;
            int col = kt + kq * 4;
            float4 v = make_float4(0.f, 0.f, 0.f, 0.f);
            if (row < M) {
                v = *(const float4*)&A[(size_t)row * 512 + col];
                int cv = col >> 7, j = col & 127, h = j >> 3;
                float inv = 1.f / (nsum[((size_t)cv * MAXN + row) * 16 + h] + 1e-16f);
                float4 bv = *(const float4*)&bcat[col];
                v.x = bv.x + v.x * inv;
                v.y = bv.y + v.y * inv;
                v.z = bv.z + v.z * inv;
                v.w = bv.w + v.w * inv;
            }
            *(float4*)&As[r][kq * 4] = tf32cvt4(v);
        }
#pragma unroll
        for (int i = 0; i < 4; i++) {
            int flat = tid + i * 256;
            int k = flat >> 5, n4 = flat & 31;
            float4 v = *(const float4*)&W[(size_t)(kt + k) * 128 + n4 * 4];
            *(float4*)&Ws[k][n4 * 4] = tf32cvt4(v);
        }
        __syncthreads();

#pragma unroll
        for (int k8 = 0; k8 < 4; k8++) {
            const int kb = k8 * 8;
            uint32_t a[2][4], b[8][2];
#pragma unroll
            for (int mt = 0; mt < 2; mt++) {
                int m = wm + mt * 16;
                a[mt][0] = __float_as_uint(As[m + g][kb + tg]);
                a[mt][1] = __float_as_uint(As[m + 8 + g][kb + tg]);
                a[mt][2] = __float_as_uint(As[m + g][kb + tg + 4]);
                a[mt][3] = __float_as_uint(As[m + 8 + g][kb + tg + 4]);
            }
#pragma unroll
            for (int nt = 0; nt < 8; nt++) {
                int n = wn + nt * 8;
                b[nt][0] = __float_as_uint(Ws[kb + tg][n + g]);
                b[nt][1] = __float_as_uint(Ws[kb + tg + 4][n + g]);
            }
#pragma unroll
            for (int mt = 0; mt < 2; mt++)
#pragma unroll
                for (int nt = 0; nt < 8; nt++)
                    mma_tf32(c[mt][nt], a[mt], b[nt]);
        }
        __syncthreads();
    }

#pragma unroll
    for (int mt = 0; mt < 2; mt++) {
#pragma unroll
        for (int nt = 0; nt < 8; nt++) {
            int row = r0 + wm + mt * 16 + g;
            int col = wn + nt * 8 + tg * 2;
            float2 bv = *(const float2*)&bias[col];
            if (row < M) {
                float2 o = make_float2(c[mt][nt][0] + bv.x, c[mt][nt][1] + bv.y);
                *(float2*)&out[(size_t)row * 128 + col] = o;
            }
            if (row + 8 < M) {
                float2 o = make_float2(c[mt][nt][2] + bv.x, c[mt][nt][3] + bv.y);
                *(float2*)&out[(size_t)(row + 8) * 128 + col] = o;
            }
        }
    }
}

// ---------------- conv0: fused (dual_attr @ We1) GEMM + edge softmax pass ------
__global__ __launch_bounds__(256)
void edge_conv0(const float* __restrict__ A /*dual_attr*/, const float* __restrict__ W /*We1*/,
                const int* __restrict__ src, const int* __restrict__ dst, int E,
                const float* __restrict__ xlr, const float* __restrict__ att,
                float* __restrict__ nsum, float* __restrict__ xcat) {
    __shared__ float smu[128 * 136];            // union: phase1 As+Ws | phase3 pre_s
    float (*As)[36]   = (float(*)[36])smu;
    float (*Ws)[136]  = (float(*)[136])(smu + 128 * 36);
    float (*pre_s)[136] = (float(*)[136])smu;

    const int tid = threadIdx.x;
    const int l = tid & 31, w = tid >> 5;
    const int g = l >> 2, tg = l & 3;
    const int wm = (w & 3) * 32;
    const int wn = (w >> 2) * 64;
    const int r0 = blockIdx.x * 128;            // first edge of tile

    float c[2][8][4];
#pragma unroll
    for (int mt = 0; mt < 2; mt++)
#pragma unroll
        for (int nt = 0; nt < 8; nt++)
#pragma unroll
            for (int i = 0; i < 4; i++) c[mt][nt][i] = 0.f;

    for (int kt = 0; kt < 128; kt += 32) {
#pragma unroll
        for (int i = 0; i < 4; i++) {
            int flat = tid + i * 256;
            int r = flat >> 3, kq = flat & 7;
            float4 v = (r0 + r < E)
                ? *(const float4*)&A[(size_t)(r0 + r) * 128 + kt + kq * 4]
                : make_float4(0.f, 0.f, 0.f, 0.f);
            *(float4*)&As[r][kq * 4] = tf32cvt4(v);
        }
#pragma unroll
        for (int i = 0; i < 4; i++) {
            int flat = tid + i * 256;
            int k = flat >> 5, n4 = flat & 31;
            float4 v = *(const float4*)&W[(size_t)(kt + k) * 128 + n4 * 4];
            *(float4*)&Ws[k][n4 * 4] = tf32cvt4(v);
        }
        __syncthreads();

#pragma unroll
        for (int k8 = 0; k8 < 4; k8++) {
            const int kb = k8 * 8;
            uint32_t a[2][4], b[8][2];
#pragma unroll
            for (int mt = 0; mt < 2; mt++) {
                int m = wm + mt * 16;
                a[mt][0] = __float_as_uint(As[m + g][kb + tg]);
                a[mt][1] = __float_as_uint(As[m + 8 + g][kb + tg]);
                a[mt][2] = __float_as_uint(As[m + g][kb + tg + 4]);
                a[mt][3] = __float_as_uint(As[m + 8 + g][kb + tg + 4]);
            }
#pragma unroll
            for (int nt = 0; nt < 8; nt++) {
                int n = wn + nt * 8;
                b[nt][0] = __float_as_uint(Ws[kb + tg][n + g]);
                b[nt][1] = __float_as_uint(Ws[kb + tg + 4][n + g]);
            }
#pragma unroll
            for (int mt = 0; mt < 2; mt++)
#pragma unroll
                for (int nt = 0; nt < 8; nt++)
                    mma_tf32(c[mt][nt], a[mt], b[nt]);
        }
        __syncthreads();
    }

    // fragments -> pre_s (As/Ws dead)
#pragma unroll
    for (int mt = 0; mt < 2; mt++) {
#pragma unroll
        for (int nt = 0; nt < 8; nt++) {
            int lr = wm + mt * 16 + g;
            int col = wn + nt * 8 + tg * 2;
            *(float2*)&pre_s[lr][col]     = make_float2(c[mt][nt][0], c[mt][nt][1]);
            *(float2*)&pre_s[lr + 8][col] = make_float2(c[mt][nt][2], c[mt][nt][3]);
        }
    }
    __syncthreads();

    // each warp handles 16 edges
#pragma unroll 4
    for (int i = 0; i < 16; i++) {
        int le = w * 16 + i;
        int e = r0 + le;
        if (e >= E) break;
        int s = src[e], d = dst[e];
        float4 a = *(const float4*)&xlr[(size_t)s * 1024 + l * 4];
        float4 b = *(const float4*)&xlr[(size_t)d * 1024 + 128 + l * 4];
        float4 p = *(const float4*)&pre_s[le][l * 4];
        float4 m = make_float4(a.x + b.x + p.x, a.y + b.y + p.y,
                               a.z + b.z + p.z, a.w + b.w + p.w);
        float4 t4 = *(const float4*)&att[l * 4];
        float lx = (m.x > 0.f) ? m.x : 0.2f * m.x;
        float ly = (m.y > 0.f) ? m.y : 0.2f * m.y;
        float lz = (m.z > 0.f) ? m.z : 0.2f * m.z;
        float lw = (m.w > 0.f) ? m.w : 0.2f * m.w;
        float partial = lx * t4.x + ly * t4.y + lz * t4.z + lw * t4.w;
        partial += __shfl_xor_sync(0xffffffffu, partial, 1);
        float ev = __expf(partial);

        if ((l & 1) == 0) {
            float* pn = &nsum[(size_t)d * 16 + (l >> 1)];
            asm volatile("red.global.add.f32 [%0], %1;" :: "l"(pn), "f"(ev) : "memory");
        }
        float* pp = &xcat[(size_t)d * 512 + l * 4];
        asm volatile("red.global.add.v4.f32 [%0], {%1,%2,%3,%4};" ::
                     "l"(pp), "f"(ev * a.x), "f"(ev * a.y),
                     "f"(ev * a.z), "f"(ev * a.w) : "memory");
    }
}

// ---------------- fused edge pass for convs 1-3 in ONE launch -------------------
struct EdgeAll {
    const int* src[3];
    const int* dst[3];
    const float* att[3];
    float* nsum[3];
    int E[3];
    int cofs[3];
    int xofs[3];
    int nb[3];      // blocks per conv
};

__global__ void edge_fused_all(EdgeAll P, const float* __restrict__ xlr,
                               float* __restrict__ xcat) {
    int b = blockIdx.x;
    int c = 0;
    if (b >= P.nb[0]) { b -= P.nb[0]; c = 1; }
    if (c == 1 && b >= P.nb[1]) { b -= P.nb[1]; c = 2; }

    const int l = threadIdx.x & 31;
    const int slot = threadIdx.x >> 5;
    const int e = b * 8 + slot;
    if (e >= P.E[c]) return;
    int s = P.src[c][e], d = P.dst[c][e];
    const int cofs = P.cofs[c];
    float4 a = *(const float4*)&xlr[(size_t)s * 1024 + cofs + l * 4];
    float4 bb = *(const float4*)&xlr[(size_t)d * 1024 + cofs + 128 + l * 4];
    float4 m = make_float4(a.x + bb.x, a.y + bb.y, a.z + bb.z, a.w + bb.w);
    float4 t4 = *(const float4*)&P.att[c][l * 4];
    float lx = (m.x > 0.f) ? m.x : 0.2f * m.x;
    float ly = (m.y > 0.f) ? m.y : 0.2f * m.y;
    float lz = (m.z > 0.f) ? m.z : 0.2f * m.z;
    float lw = (m.w > 0.f) ? m.w : 0.2f * m.w;
    float partial = lx * t4.x + ly * t4.y + lz * t4.z + lw * t4.w;
    partial += __shfl_xor_sync(0xffffffffu, partial, 1);
    float ev = __expf(partial);

    if ((l & 1) == 0) {
        float* pn = &P.nsum[c][(size_t)d * 16 + (l >> 1)];
        asm volatile("red.global.add.f32 [%0], %1;" :: "l"(pn), "f"(ev) : "memory");
    }
    float* p = &xcat[(size_t)d * 512 + P.xofs[c] + l * 4];
    asm volatile("red.global.add.v4.f32 [%0], {%1,%2,%3,%4};" ::
                 "l"(p), "f"(ev * a.x), "f"(ev * a.y),
                 "f"(ev * a.z), "f"(ev * a.w) : "memory");
}

// ---------------- persistent edge MLP (tensor-core matvec batch) ---------------
// 1024 threads (32 warps/SM instead of 16 — same 204KB smem, double latency
// hiding for the xf gathers + shfl LN chains). Warp grid 2m x 16n, tile 32x8.
__global__ __launch_bounds__(1024, 1)
void edge_mlp(const int* __restrict__ src, const int* __restrict__ dst, int E,
              const float* __restrict__ xf,
              const float* __restrict__ lng, const float* __restrict__ lnb,
              const float* __restrict__ W, const float* __restrict__ mlpb,
              const float* __restrict__ eattr, float* __restrict__ out) {
    extern __shared__ float sm[];
    float (*Wks)[136] = (float(*)[136])sm;                 // 256*136
    float (*ps)[260]  = (float(*)[260])(sm + 256 * 136);   // 64*260
    float* lg = sm + 256 * 136 + 64 * 260;                 // 256
    float* lb = lg + 256;                                  // 256
    float* mb = lb + 256;                                  // 128

    const int tid = threadIdx.x;
    const int l = tid & 31, w = tid >> 5;          // 32 warps
    const int g = l >> 2, tg = l & 3;
    const int wm = (w & 1) * 32;                   // 2 m-warps
    const int wn = (w >> 1) * 8;                   // 16 n-warps x 8 cols

    // stage mlp_W (tf32) + consts, coalesced: 8192 float4s over 1024 threads
#pragma unroll
    for (int i = 0; i < 8; i++) {
        int flat = tid + i * 1024;
        int k = flat >> 5, n4 = flat & 31;
        float4 v = *(const float4*)&W[(size_t)k * 128 + n4 * 4];
        *(float4*)&Wks[k][n4 * 4] = tf32cvt4(v);
    }
    if (tid < 256) { lg[tid] = lng[tid]; lb[tid] = lnb[tid]; }
    if (tid < 128) mb[tid] = mlpb[tid];
    __syncthreads();

    for (int base = blockIdx.x * 64; base < E; base += gridDim.x * 64) {
        // ---- LN phase: 2 edges per warp; batch gathers first ----
        int ss[2], dd[2];
#pragma unroll
        for (int e = 0; e < 2; e++) {
            int ge = base + w * 2 + e;
            ss[e] = (ge < E) ? src[ge] : 0;
            dd[e] = (ge < E) ? dst[ge] : 0;
        }
        float4 A4[2], B4[2];
#pragma unroll
        for (int e = 0; e < 2; e++) {
            A4[e] = *(const float4*)&xf[(size_t)ss[e] * 128 + l * 4];
            B4[e] = *(const float4*)&xf[(size_t)dd[e] * 128 + l * 4];
        }
#pragma unroll
        for (int e = 0; e < 2; e++) {
            int le = w * 2 + e;
            int ge = base + le;
            float4 a = A4[e], b = B4[e];
            float4 ra, rb;
            if (ge < E) {
                float sum = a.x + a.y + a.z + a.w + b.x + b.y + b.z + b.w;
                float sq  = a.x * a.x + a.y * a.y + a.z * a.z + a.w * a.w
                          + b.x * b.x + b.y * b.y + b.z * b.z + b.w * b.w;
#pragma unroll
                for (int off = 16; off; off >>= 1) {
                    sum += __shfl_xor_sync(0xffffffffu, sum, off);
                    sq  += __shfl_xor_sync(0xffffffffu, sq, off);
                }
                float mu = sum * (1.f / 256.f);
                float var = sq * (1.f / 256.f) - mu * mu;
                float rs = rsqrtf(var + 1e-5f);
                float4 ga = *(const float4*)&lg[l * 4];
                float4 ba = *(const float4*)&lb[l * 4];
                float4 gb = *(const float4*)&lg[128 + l * 4];
                float4 bb = *(const float4*)&lb[128 + l * 4];
                ra.x = fmaxf(0.f, (a.x - mu) * rs * ga.x + ba.x);
                ra.y = fmaxf(0.f, (a.y - mu) * rs * ga.y + ba.y);
                ra.z = fmaxf(0.f, (a.z - mu) * rs * ga.z + ba.z);
                ra.w = fmaxf(0.f, (a.w - mu) * rs * ga.w + ba.w);
                rb.x = fmaxf(0.f, (b.x - mu) * rs * gb.x + bb.x);
                rb.y = fmaxf(0.f, (b.y - mu) * rs * gb.y + bb.y);
                rb.z = fmaxf(0.f, (b.z - mu) * rs * gb.z + bb.z);
                rb.w = fmaxf(0.f, (b.w - mu) * rs * gb.w + bb.w);
            } else {
                ra = rb = make_float4(0.f, 0.f, 0.f, 0.f);
            }
            *(float4*)&ps[le][l * 4]       = tf32cvt4(ra);
            *(float4*)&ps[le][128 + l * 4] = tf32cvt4(rb);
        }
        __syncthreads();

        // ---- block GEMM [64,256]@[256,128]; warp tile 32x8 ----
        float c[2][4];
#pragma unroll
        for (int mt = 0; mt < 2; mt++)
#pragma unroll
            for (int i = 0; i < 4; i++) c[mt][i] = 0.f;

#pragma unroll 4
        for (int k8 = 0; k8 < 32; k8++) {
            const int kb = k8 * 8;
            uint32_t a[2][4], b[2];
#pragma unroll
            for (int mt = 0; mt < 2; mt++) {
                int m = wm + mt * 16;
                a[mt][0] = __float_as_uint(ps[m + g][kb + tg]);
                a[mt][1] = __float_as_uint(ps[m + 8 + g][kb + tg]);
                a[mt][2] = __float_as_uint(ps[m + g][kb + tg + 4]);
                a[mt][3] = __float_as_uint(ps[m + 8 + g][kb + tg + 4]);
            }
            b[0] = __float_as_uint(Wks[kb + tg][wn + g]);
            b[1] = __float_as_uint(Wks[kb + tg + 4][wn + g]);
#pragma unroll
            for (int mt = 0; mt < 2; mt++)
                mma_tf32(c[mt], a[mt], b);
        }

        // ---- epilogue: + mlp_b + edge_attr, store ----
#pragma unroll
        for (int mt = 0; mt < 2; mt++) {
            int le = wm + mt * 16 + g;
            int col = wn + tg * 2;
            float2 bv = *(const float2*)&mb[col];
            int ge0 = base + le;
            int ge1 = ge0 + 8;
            if (ge0 < E) {
                float2 ea = *(const float2*)&eattr[(size_t)ge0 * 128 + col];
                float2 o = make_float2(c[mt][0] + bv.x + ea.x,
                                       c[mt][1] + bv.y + ea.y);
                *(float2*)&out[(size_t)ge0 * 128 + col] = o;
            }
            if (ge1 < E) {
                float2 ea = *(const float2*)&eattr[(size_t)ge1 * 128 + col];
                float2 o = make_float2(c[mt][2] + bv.x + ea.x,
                                       c[mt][3] + bv.y + ea.y);
                *(float2*)&out[(size_t)ge1 * 128 + col] = o;
            }
        }
        __syncthreads();   // ps reused next batch
    }
}

// dual_out[i] = (idx==E) ? ones : edge_attr_new[idx]
__global__ void dual_gather(const int* __restrict__ idx, int M, int E,
                            const float* __restrict__ ea, float* __restrict__ out) {
    int tid = blockIdx.x * blockDim.x + threadIdx.x;
    if (tid >= M * 32) return;
    int i = tid >> 5, l = tid & 31;
    int id = idx[i];
    float4 v;
    if (id >= E) v = make_float4(1.f, 1.f, 1.f, 1.f);
    else         v = *(const float4*)&ea[(size_t)id * 128 + l * 4];
    *(float4*)&out[(size_t)i * 128 + l * 4] = v;
}

// ---------------- host orchestration ------------------------------------------

static const int MLP_SMEM = (256 * 136 + 64 * 260 + 256 + 256 + 128) * 4;  // ~204 KB

extern "C" void kernel_launch(void* const* d_in, const int* in_sizes, int n_in,
                              void* d_out, int out_size) {
    const float* x         = (const float*)d_in[0];
    const int*   ei[4]     = {(const int*)d_in[1], (const int*)d_in[2],
                              (const int*)d_in[3], (const int*)d_in[4]};
    const float* dual_attr = (const float*)d_in[5];
    const float* edge_attr = (const float*)d_in[6];
    const int*   oemap     = (const int*)d_in[7];

    const float *Wl[4], *Wr[4], *att[4], *bb[4];
    int p = 8;
    for (int c = 0; c < 4; c++) {
        Wl[c]  = (const float*)d_in[p++];
        Wr[c]  = (const float*)d_in[p++];
        att[c] = (const float*)d_in[p++];
        bb[c]  = (const float*)d_in[p++];
    }
    const float* We1    = (const float*)d_in[24];
    const float* fuse_W = (const float*)d_in[25];
    const float* fuse_b = (const float*)d_in[26];
    const float* ln_g   = (const float*)d_in[27];
    const float* ln_b   = (const float*)d_in[28];
    const float* mlp_W  = (const float*)d_in[29];
    const float* mlp_b  = (const float*)d_in[30];

    const int N     = in_sizes[0] / 128;
    const int Ec[4] = {in_sizes[1] / 2, in_sizes[2] / 2, in_sizes[3] / 2, in_sizes[4] / 2};
    const int M_oe  = in_sizes[7];
    const int E1    = Ec[0];

    float *xlr, *wcat, *bcat, *xcat, *nsum;
    cudaGetSymbolAddress((void**)&xlr,  g_xlr);
    cudaGetSymbolAddress((void**)&wcat, g_wcat);
    cudaGetSymbolAddress((void**)&bcat, g_bcat);
    cudaGetSymbolAddress((void**)&xcat, g_xcat);
    cudaGetSymbolAddress((void**)&nsum, g_nsum);

    cudaFuncSetAttribute(edge_mlp, cudaFuncAttributeMaxDynamicSharedMemorySize, MLP_SMEM);

    // zero accumulators (graph-capturable async memsets)
    cudaMemsetAsync(xcat, 0, (size_t)N * 512 * sizeof(float), 0);
    cudaMemsetAsync(nsum, 0, (size_t)4 * MAXN * 16 * sizeof(float), 0);

    // pack (Wl|Wr) x 4 -> wcat [128,1024]; biases -> bcat[512]
    pack_w<<<(128 * 1024 + 255) / 256, 256>>>(Wl[0], Wr[0], Wl[1], Wr[1],
                                              Wl[2], Wr[2], Wl[3], Wr[3], wcat,
                                              bb[0], bb[1], bb[2], bb[3], bcat);

    // one wide GEMM for all 8 node projections: xlr = x @ wcat
    {
        dim3 grid((N + 127) / 128, 8);
        gemm_mma<128, 1024, 1024><<<grid, 256>>>(x, wcat, nullptr, xlr, N);
    }

    // conv0: fused (dual_attr @ We1) + edge softmax scatter (pre never hits DRAM)
    edge_conv0<<<(E1 + 127) / 128, 256>>>(dual_attr, We1, ei[0], ei[0] + E1, E1,
                                          xlr, att[0], nsum, xcat);

    // convs 1..3 in one launch
    {
        EdgeAll P;
        int total_nb = 0;
        for (int c = 1; c < 4; c++) {
            int i = c - 1;
            P.src[i]  = ei[c];
            P.dst[i]  = ei[c] + Ec[c];
            P.att[i]  = att[c];
            P.nsum[i] = nsum + (size_t)c * MAXN * 16;
            P.E[i]    = Ec[c];
            P.cofs[i] = c * 256;
            P.xofs[i] = c * 128;
            P.nb[i]   = (Ec[c] + 7) / 8;
            total_nb += P.nb[i];
        }
        edge_fused_all<<<total_nb, 256>>>(P, xlr, xcat);
    }

    // fuse GEMM with inline normalization: xf = (xcat/nsum + bcat) @ fuse_W + fuse_b
    float* xf = (float*)d_out;
    gemm_fuse<<<(N + 127) / 128, 256>>>(xcat, nsum, bcat, fuse_W, fuse_b, xf, N);

    // edge MLP -> output section 1 (persistent, 32 warps/SM)
    float* eout = (float*)d_out + (size_t)N * 128;
    edge_mlp<<<148, 1024, MLP_SMEM>>>(ei[0], ei[0] + E1, E1, xf, ln_g, ln_b,
                                      mlp_W, mlp_b, edge_attr, eout);

    // dual gather -> output section 2
    float* dout = eout + (size_t)E1 * 128;
    dual_gather<<<(M_oe * 32 + 255) / 256, 256>>>(oemap, M_oe, E1, eout, dout);
}